// round 2
// baseline (speedup 1.0000x reference)
#include <cuda_runtime.h>
#include <cuda_bf16.h>
#include <math.h>

#define NN 50000
#define NODE_F 128
#define EPG 4
typedef unsigned long long ull;

// ---------------- device scratch ----------------
__device__ float g_pre [NN * 128];    // x @ W1a + b1
__device__ float g_agg [NN * 128];    // sum relu(h1) per target
__device__ float g_cnt [NN];
__device__ float g_Wc  [128 * 384];   // W2 @ W_ih^T, [k][o]
__device__ float g_cvec[384];         // b2 @ W_ih^T
__device__ float g_owT [128 * 128];   // out_w^T [k][o]
__device__ float g_mem [NN * 128];

// ---------------- packed f32x2 helpers ----------------
__device__ __forceinline__ ull splat2(float a) {
    ull r; unsigned u = __float_as_uint(a);
    asm("mov.b64 %0, {%1,%1};" : "=l"(r) : "r"(u));
    return r;
}
__device__ __forceinline__ void ffma2(ull& d, ull a, ull b) {
    asm("fma.rn.f32x2 %0, %1, %2, %3;" : "=l"(d) : "l"(a), "l"(b), "l"(d));
}
__device__ __forceinline__ float2 unpack2(ull v) {
    float2 f;
    asm("mov.b64 {%0,%1}, %2;" : "=f"(f.x), "=f"(f.y) : "l"(v));
    return f;
}
__device__ __forceinline__ float sigm(float x) { return 1.f / (1.f + expf(-x)); }

// ---------------- prep: combined weights + transpose ----------------
__global__ void prep_kernel(const float* __restrict__ msg_w2,
                            const float* __restrict__ msg_b2,
                            const float* __restrict__ w_ih,
                            const float* __restrict__ out_w) {
    int idx = blockIdx.x * blockDim.x + threadIdx.x;
    if (idx < 128 * 384) {
        int i = idx / 384, o = idx % 384;
        const float* a = msg_w2 + i * 128;
        const float* b = w_ih + o * 128;
        float s = 0.f;
        #pragma unroll 8
        for (int k = 0; k < 128; k++) s = fmaf(a[k], b[k], s);
        g_Wc[i * 384 + o] = s;
    } else if (idx < 128 * 384 + 384) {
        int o = idx - 128 * 384;
        const float* b = w_ih + o * 128;
        float s = 0.f;
        #pragma unroll 8
        for (int k = 0; k < 128; k++) s = fmaf(msg_b2[k], b[k], s);
        g_cvec[o] = s;
    } else if (idx < 128 * 384 + 384 + 128 * 128) {
        int j = idx - (128 * 384 + 384);
        int k = j / 128, o = j % 128;
        g_owT[k * 128 + o] = out_w[o * 128 + k];
    }
}

// ---------------- tiled fp32x2 GEMM: C[M,128] = A[M,128] @ B[128,128] + bias ----------------
__global__ void __launch_bounds__(256) gemm128_kernel(
    const float* __restrict__ A, const float* __restrict__ B,
    const float* __restrict__ bias, float* __restrict__ C, int M) {
    __shared__ float As[64 * 16];
    __shared__ float Bs[16 * 128];
    const int t = threadIdx.x;
    const int m0 = blockIdx.x * 64;
    const int cgrp = t & 31, rgrp = t >> 5;

    ulonglong2 acc[8];
    #pragma unroll
    for (int i = 0; i < 8; i++) { acc[i].x = 0ull; acc[i].y = 0ull; }

    const int arow = t >> 2, ac4 = t & 3;
    const int brow1 = t >> 5, bc1 = t & 31;
    const int brow2 = (t + 256) >> 5, bc2 = (t + 256) & 31;

    for (int kk0 = 0; kk0 < 128; kk0 += 16) {
        {
            int gm = m0 + arow;
            float4 v = make_float4(0.f, 0.f, 0.f, 0.f);
            if (gm < M) v = reinterpret_cast<const float4*>(A + (size_t)gm * 128 + kk0)[ac4];
            reinterpret_cast<float4*>(As)[arow * 4 + ac4] = v;
        }
        reinterpret_cast<float4*>(Bs)[t] =
            reinterpret_cast<const float4*>(B + (size_t)(kk0 + brow1) * 128)[bc1];
        reinterpret_cast<float4*>(Bs)[t + 256] =
            reinterpret_cast<const float4*>(B + (size_t)(kk0 + brow2) * 128)[bc2];
        __syncthreads();

        #pragma unroll 8
        for (int kk = 0; kk < 16; kk++) {
            ulonglong2 bv = reinterpret_cast<const ulonglong2*>(Bs)[kk * 32 + cgrp];
            #pragma unroll
            for (int i = 0; i < 8; i++) {
                ull aa = splat2(As[(rgrp * 8 + i) * 16 + kk]);
                ffma2(acc[i].x, aa, bv.x);
                ffma2(acc[i].y, aa, bv.y);
            }
        }
        __syncthreads();
    }

    float4 bv = reinterpret_cast<const float4*>(bias)[cgrp];
    #pragma unroll
    for (int i = 0; i < 8; i++) {
        int gm = m0 + rgrp * 8 + i;
        if (gm < M) {
            float2 lo = unpack2(acc[i].x), hi = unpack2(acc[i].y);
            float4 v = make_float4(lo.x + bv.x, lo.y + bv.y, hi.x + bv.z, hi.y + bv.w);
            reinterpret_cast<float4*>(C + (size_t)gm * 128)[cgrp] = v;
        }
    }
}

// ---------------- edge kernel ----------------
__global__ void __launch_bounds__(256) edge_kernel(
    const float* __restrict__ edge_attr, const float* __restrict__ t_arr,
    const int* __restrict__ src_idx, const int* __restrict__ tgt_idx,
    const float* __restrict__ msg_w1,
    const float* __restrict__ time_w, const float* __restrict__ time_b, int E)
{
    __shared__ ulonglong2 sW[48 * 32];     // rows 128..175 of msg_w1, packed pairs
    __shared__ ull sV[8][EPG][48];         // pre-splatted broadcast operands
    __shared__ float stw[16], stb[16];
    const int tid = threadIdx.x;
    if (tid < 16) { stw[tid] = time_w[tid]; stb[tid] = time_b[tid]; }
    for (int i = tid; i < 48 * 32; i += 256) {
        int r = i >> 5, c = i & 31;
        sW[i] = reinterpret_cast<const ulonglong2*>(msg_w1 + (size_t)(128 + r) * 128)[c];
    }
    __syncthreads();

    const int lane = tid & 31;
    const int wrp = tid >> 5;
    const int e0 = (blockIdx.x * 8 + wrp) * EPG;
    if (e0 >= E) return;

    int tg[EPG]; bool val[EPG];
    ulonglong2 acc[EPG];
    #pragma unroll
    for (int i = 0; i < EPG; i++) {
        int e = min(e0 + i, E - 1);
        val[i] = (e0 + i) < E;
        float ea = edge_attr[(size_t)e * 32 + lane];
        sV[wrp][i][lane] = splat2(ea);
        if (lane < 16) {
            float tv = t_arr[e];
            sV[wrp][i][32 + lane] = splat2(cosf(fmaf(tv, stw[lane], stb[lane])));
        }
        int s = src_idx[e];
        tg[i] = tgt_idx[e];
        acc[i] = reinterpret_cast<const ulonglong2*>(g_pre + (size_t)s * 128)[lane];
    }
    __syncwarp();

    #pragma unroll 8
    for (int k = 0; k < 48; k++) {
        ulonglong2 w = sW[k * 32 + lane];
        #pragma unroll
        for (int i = 0; i < EPG; i++) {
            ull a = sV[wrp][i][k];
            ffma2(acc[i].x, a, w.x);
            ffma2(acc[i].y, a, w.y);
        }
    }

    #pragma unroll
    for (int i = 0; i < EPG; i++) {
        if (!val[i]) continue;
        float2 lo = unpack2(acc[i].x), hi = unpack2(acc[i].y);
        float vx = fmaxf(lo.x, 0.f), vy = fmaxf(lo.y, 0.f);
        float vz = fmaxf(hi.x, 0.f), vw = fmaxf(hi.y, 0.f);
        float* dst = g_agg + (size_t)tg[i] * 128 + lane * 4;
        asm volatile("red.global.add.v4.f32 [%0], {%1,%2,%3,%4};"
                     :: "l"(dst), "f"(vx), "f"(vy), "f"(vz), "f"(vw) : "memory");
    }
    if (lane == 0) {
        #pragma unroll
        for (int i = 0; i < EPG; i++)
            if (val[i]) atomicAdd(g_cnt + tg[i], 1.0f);
    }
}

// ---------------- fused node kernel: mean + (agg@Wc) + gates -> mem ----------------
__global__ void __launch_bounds__(256) node_kernel(
    const float* __restrict__ b_ih, const float* __restrict__ b_hh, int Nn)
{
    __shared__ float As[64 * 128];
    __shared__ float Bs[16 * 128];
    __shared__ float maskS[64];
    const int t = threadIdx.x;
    const int m0 = blockIdx.x * 64;

    // stage A = mean-scaled agg
    #pragma unroll
    for (int it = 0; it < 8; it++) {
        int idx = t + it * 256;          // 0..2047 float4s
        int row = idx >> 5, c4 = idx & 31;
        int gm = m0 + row;
        float4 v = make_float4(0.f, 0.f, 0.f, 0.f);
        if (gm < Nn) {
            float cnt = g_cnt[gm];
            float inv = 1.f / fmaxf(cnt, 1.f);
            v = reinterpret_cast<const float4*>(g_agg + (size_t)gm * 128)[c4];
            v.x *= inv; v.y *= inv; v.z *= inv; v.w *= inv;
            if (c4 == 0) maskS[row] = (cnt > 0.f) ? 1.f : 0.f;
        } else if (c4 == 0) maskS[row] = 0.f;
        reinterpret_cast<float4*>(As)[idx] = v;
    }
    __syncthreads();

    const int cgrp = t & 31, rgrp = t >> 5;
    const int brow1 = t >> 5, bc1 = t & 31;
    const int brow2 = (t + 256) >> 5, bc2 = (t + 256) & 31;
    const int col = cgrp * 4;

    float rn[8][4];   // holds r after tile0, then n after tile2

    // run one 128-col gate tile of (A @ Wc): result -> pre[8][4] incl. bias/cvec
    auto run_tile = [&](int gt, float pre[8][4]) {
        ulonglong2 acc[8];
        #pragma unroll
        for (int i = 0; i < 8; i++) { acc[i].x = 0ull; acc[i].y = 0ull; }
        for (int kk0 = 0; kk0 < 128; kk0 += 16) {
            reinterpret_cast<float4*>(Bs)[t] =
                reinterpret_cast<const float4*>(g_Wc + (size_t)(kk0 + brow1) * 384 + gt * 128)[bc1];
            reinterpret_cast<float4*>(Bs)[t + 256] =
                reinterpret_cast<const float4*>(g_Wc + (size_t)(kk0 + brow2) * 384 + gt * 128)[bc2];
            __syncthreads();
            #pragma unroll 8
            for (int kk = 0; kk < 16; kk++) {
                ulonglong2 bv = reinterpret_cast<const ulonglong2*>(Bs)[kk * 32 + cgrp];
                #pragma unroll
                for (int i = 0; i < 8; i++) {
                    ull aa = splat2(As[(rgrp * 8 + i) * 128 + kk0 + kk]);
                    ffma2(acc[i].x, aa, bv.x);
                    ffma2(acc[i].y, aa, bv.y);
                }
            }
            __syncthreads();
        }
        float4 bi = reinterpret_cast<const float4*>(b_ih + gt * 128)[cgrp];
        float4 cv = reinterpret_cast<const float4*>(g_cvec + gt * 128)[cgrp];
        #pragma unroll
        for (int i = 0; i < 8; i++) {
            float m = maskS[rgrp * 8 + i];
            float2 lo = unpack2(acc[i].x), hi = unpack2(acc[i].y);
            pre[i][0] = lo.x + bi.x + m * cv.x;
            pre[i][1] = lo.y + bi.y + m * cv.y;
            pre[i][2] = hi.x + bi.z + m * cv.z;
            pre[i][3] = hi.y + bi.w + m * cv.w;
        }
    };

    float pre[8][4];
    float4 bh0 = reinterpret_cast<const float4*>(b_hh)[cgrp];        // r bias (hh)
    float4 bh2 = reinterpret_cast<const float4*>(b_hh + 256)[cgrp];  // n bias (hh)
    float4 bh1 = reinterpret_cast<const float4*>(b_hh + 128)[cgrp];  // z bias (hh)

    run_tile(0, pre);   // r
    #pragma unroll
    for (int i = 0; i < 8; i++) {
        rn[i][0] = sigm(pre[i][0] + bh0.x);
        rn[i][1] = sigm(pre[i][1] + bh0.y);
        rn[i][2] = sigm(pre[i][2] + bh0.z);
        rn[i][3] = sigm(pre[i][3] + bh0.w);
    }
    run_tile(2, pre);   // n = tanh(i_n + r * b_hh_n)
    #pragma unroll
    for (int i = 0; i < 8; i++) {
        rn[i][0] = tanhf(pre[i][0] + rn[i][0] * bh2.x);
        rn[i][1] = tanhf(pre[i][1] + rn[i][1] * bh2.y);
        rn[i][2] = tanhf(pre[i][2] + rn[i][2] * bh2.z);
        rn[i][3] = tanhf(pre[i][3] + rn[i][3] * bh2.w);
    }
    run_tile(1, pre);   // z; mem = (1-z)*n
    #pragma unroll
    for (int i = 0; i < 8; i++) {
        int gm = m0 + rgrp * 8 + i;
        if (gm < Nn) {
            float4 v;
            v.x = (1.f - sigm(pre[i][0] + bh1.x)) * rn[i][0];
            v.y = (1.f - sigm(pre[i][1] + bh1.y)) * rn[i][1];
            v.z = (1.f - sigm(pre[i][2] + bh1.z)) * rn[i][2];
            v.w = (1.f - sigm(pre[i][3] + bh1.w)) * rn[i][3];
            reinterpret_cast<float4*>(g_mem + (size_t)gm * 128)[cgrp] = v;
        }
    }
}

// ---------------- launch ----------------
extern "C" void kernel_launch(void* const* d_in, const int* in_sizes, int n_in,
                              void* d_out, int out_size) {
    const float* x         = (const float*)d_in[0];
    const float* edge_attr = (const float*)d_in[1];
    const float* t_arr     = (const float*)d_in[2];
    const float* time_w    = (const float*)d_in[3];
    const float* time_b    = (const float*)d_in[4];
    const float* msg_w1    = (const float*)d_in[5];
    const float* msg_b1    = (const float*)d_in[6];
    const float* msg_w2    = (const float*)d_in[7];
    const float* msg_b2    = (const float*)d_in[8];
    const float* w_ih      = (const float*)d_in[9];
    const float* b_ih      = (const float*)d_in[11];
    const float* b_hh      = (const float*)d_in[12];
    const float* out_w     = (const float*)d_in[13];
    const float* out_b     = (const float*)d_in[14];
    const int*   ei        = (const int*)d_in[15];
    float* out = (float*)d_out;

    const int E = in_sizes[15] / 2;
    const int N = in_sizes[0] / NODE_F;
    const int* src = ei;
    const int* tgt = ei + E;

    float *pre, *agg, *cnt, *owT, *mem;
    cudaGetSymbolAddress((void**)&pre, g_pre);
    cudaGetSymbolAddress((void**)&agg, g_agg);
    cudaGetSymbolAddress((void**)&cnt, g_cnt);
    cudaGetSymbolAddress((void**)&owT, g_owT);
    cudaGetSymbolAddress((void**)&mem, g_mem);

    cudaMemsetAsync(agg, 0, (size_t)N * 128 * sizeof(float));
    cudaMemsetAsync(cnt, 0, (size_t)N * sizeof(float));

    {
        int total = 128 * 384 + 384 + 128 * 128;
        prep_kernel<<<(total + 255) / 256, 256>>>(msg_w2, msg_b2, w_ih, out_w);
    }

    // pre = x @ W1a + msg_b1
    gemm128_kernel<<<(N + 63) / 64, 256>>>(x, msg_w1, msg_b1, pre, N);

    // edge pipeline
    {
        int warps = (E + EPG - 1) / EPG;
        edge_kernel<<<(warps + 7) / 8, 256>>>(edge_attr, t_arr, src, tgt,
                                              msg_w1, time_w, time_b, E);
    }

    // fused mean + gi GEMM + GRU gates -> mem
    node_kernel<<<(N + 63) / 64, 256>>>(b_ih, b_hh, N);

    // out = mem @ out_w^T + out_b
    gemm128_kernel<<<(N + 63) / 64, 256>>>(mem, owT, out_b, out, N);
}